// round 2
// baseline (speedup 1.0000x reference)
#include <cuda_runtime.h>

#define TT 256
#define BB 64
#define DD 1024
#define HH 1024
#define G4 4096
#define EPSF 0.01f

// ---------------- device scratch (static: allocation-free kernel_launch) ---
static __device__ float g_G[(size_t)TT * BB * G4];     // x@W_ih.T + b_ih + b_hh   (256 MB)
static __device__ float g_xn2[TT * BB];                // |x_t|^2 per (t,b)
static __device__ float g_hn2[(TT + 1) * BB];          // |h_t|^2 per (t,b), accumulated
static __device__ float g_h[2][BB * HH];               // ping-pong hidden
static __device__ float g_dh[2][BB * HH];              // ping-pong tangent hidden
static __device__ float g_c[BB * HH];
static __device__ float g_dc[BB * HH];

// ---------------- init: zero states & norm accumulators (runs every replay) --
__global__ void init_kernel() {
    int idx = blockIdx.x * blockDim.x + threadIdx.x;
    int stride = gridDim.x * blockDim.x;
    for (int i = idx; i < BB * HH; i += stride) {
        g_h[0][i] = 0.f; g_h[1][i] = 0.f;
        g_dh[0][i] = 0.f; g_dh[1][i] = 0.f;
        g_c[i] = 0.f; g_dc[i] = 0.f;
    }
    for (int i = idx; i < (TT + 1) * BB; i += stride) g_hn2[i] = 0.f;
}

// ---------------- |x_t|^2 ---------------------------------------------------
__global__ void xnorm_kernel(const float* __restrict__ x) {
    int row = blockIdx.x;                 // t*BB + b
    const float* xr = x + (size_t)row * DD;
    float s = 0.f;
    for (int i = threadIdx.x; i < DD; i += blockDim.x) { float v = xr[i]; s += v * v; }
    __shared__ float red[8];
    #pragma unroll
    for (int o = 16; o > 0; o >>= 1) s += __shfl_xor_sync(0xffffffffu, s, o);
    if ((threadIdx.x & 31) == 0) red[threadIdx.x >> 5] = s;
    __syncthreads();
    if (threadIdx.x < 8) {
        s = red[threadIdx.x];
        #pragma unroll
        for (int o = 4; o > 0; o >>= 1) s += __shfl_xor_sync(0xffu, s, o);
        if (threadIdx.x == 0) g_xn2[row] = s;
    }
}

// ---------------- precompute GEMM: G = x @ W_ih.T + (b_ih + b_hh) -----------
// M=16384, N=4096, K=1024. 128x128 tile, BK=8, 256 threads, 8x8 micro.
__global__ void __launch_bounds__(256) pre_gemm(const float* __restrict__ x,
                                                const float* __restrict__ Wih,
                                                const float* __restrict__ bih,
                                                const float* __restrict__ bhh) {
    __shared__ __align__(16) float As[128 * 12];   // [m][k] pad 12
    __shared__ __align__(16) float Bs[8 * 132];    // [k][n] pad 132
    const int n0 = blockIdx.x * 128;
    const int m0 = blockIdx.y * 128;
    const int tid = threadIdx.x;
    const int tx = tid & 15, ty = tid >> 4;        // 16x16 thread grid
    const int lrow = tid >> 1, lhalf = tid & 1;

    float acc[8][8];
    #pragma unroll
    for (int i = 0; i < 8; i++)
        #pragma unroll
        for (int j = 0; j < 8; j++) acc[i][j] = 0.f;

    const float* aptr = x   + (size_t)(m0 + lrow) * DD + lhalf * 4;
    const float* bptr = Wih + (size_t)(n0 + lrow) * DD + lhalf * 4;

    for (int k0 = 0; k0 < DD; k0 += 8) {
        float4 av = *(const float4*)(aptr + k0);
        float4 bv = *(const float4*)(bptr + k0);
        *(float4*)(As + lrow * 12 + lhalf * 4) = av;
        Bs[(lhalf * 4 + 0) * 132 + lrow] = bv.x;
        Bs[(lhalf * 4 + 1) * 132 + lrow] = bv.y;
        Bs[(lhalf * 4 + 2) * 132 + lrow] = bv.z;
        Bs[(lhalf * 4 + 3) * 132 + lrow] = bv.w;
        __syncthreads();
        #pragma unroll
        for (int kq = 0; kq < 2; kq++) {
            float4 a[8];
            #pragma unroll
            for (int i = 0; i < 8; i++)
                a[i] = *(const float4*)(As + (8 * ty + i) * 12 + kq * 4);
            float4 b0[4], b1[4];
            #pragma unroll
            for (int e = 0; e < 4; e++) {
                b0[e] = *(const float4*)(Bs + (kq * 4 + e) * 132 + 8 * tx);
                b1[e] = *(const float4*)(Bs + (kq * 4 + e) * 132 + 8 * tx + 4);
            }
            #pragma unroll
            for (int i = 0; i < 8; i++) {
                const float* ai = reinterpret_cast<const float*>(&a[i]);
                #pragma unroll
                for (int e = 0; e < 4; e++) {
                    const float* p0 = reinterpret_cast<const float*>(&b0[e]);
                    const float* p1 = reinterpret_cast<const float*>(&b1[e]);
                    float av_ = ai[e];
                    #pragma unroll
                    for (int j = 0; j < 4; j++) {
                        acc[i][j]     += av_ * p0[j];
                        acc[i][4 + j] += av_ * p1[j];
                    }
                }
            }
        }
        __syncthreads();
    }

    float bsum[8];
    #pragma unroll
    for (int j = 0; j < 8; j++) {
        int n = n0 + 8 * tx + j;
        bsum[j] = bih[n] + bhh[n];
    }
    #pragma unroll
    for (int i = 0; i < 8; i++) {
        size_t row = (size_t)(m0 + 8 * ty + i);
        float* dst = g_G + row * G4 + n0 + 8 * tx;
        float4 o0, o1;
        o0.x = acc[i][0] + bsum[0]; o0.y = acc[i][1] + bsum[1];
        o0.z = acc[i][2] + bsum[2]; o0.w = acc[i][3] + bsum[3];
        o1.x = acc[i][4] + bsum[4]; o1.y = acc[i][5] + bsum[5];
        o1.z = acc[i][6] + bsum[6]; o1.w = acc[i][7] + bsum[7];
        *(float4*)dst       = o0;
        *(float4*)(dst + 4) = o1;
    }
}

// ---------------- per-step fused kernel --------------------------------------
// Grid 128 CTAs x 128 threads. CTA owns 8 h-columns (n0..n0+7) across all 4
// gates -> 32 W_hh rows. GEMM A = [h(64); dh(64)] (128 x 1024), output 128x32,
// then fused LSTM+MAGE elementwise update for those columns.
__global__ void __launch_bounds__(128) step_kernel(int t, const float* __restrict__ g,
                                                   const float* __restrict__ Whh,
                                                   float* __restrict__ out) {
    __shared__ __align__(16) float As[128 * 36];   // GEMM A tile; later pre_s[128][33]
    __shared__ __align__(16) float Ws[32 * 36];    // W tile [r][k]
    const int n0 = blockIdx.x * 8;
    const int tid = threadIdx.x;
    const int tx = tid & 7, ty = tid >> 3;         // tx<8 (cols/4), ty<16 (rows/8)
    const float* hprev  = g_h[t & 1];
    const float* dhprev = g_dh[t & 1];

    float acc[8][4];
    #pragma unroll
    for (int i = 0; i < 8; i++)
        #pragma unroll
        for (int j = 0; j < 4; j++) acc[i][j] = 0.f;

    for (int k0 = 0; k0 < HH; k0 += 32) {
        // load A tile: 128 rows x 32 k (h rows 0-63, dh rows 64-127)
        #pragma unroll
        for (int l = 0; l < 8; l++) {
            int fl = tid + l * 128;
            int m = fl >> 3, f4 = (fl & 7) << 2;
            const float* src = (m < BB) ? (hprev + m * HH) : (dhprev + (m - BB) * HH);
            *(float4*)(As + m * 36 + f4) = *(const float4*)(src + k0 + f4);
        }
        // load W tile: 32 rows (4 gates x 8 cols) x 32 k
        #pragma unroll
        for (int l = 0; l < 2; l++) {
            int fl = tid + l * 128;
            int r = fl >> 3, f4 = (fl & 7) << 2;
            int q = r >> 3, j = r & 7;
            const float* src = Whh + ((size_t)q * HH + n0 + j) * HH;
            *(float4*)(Ws + r * 36 + f4) = *(const float4*)(src + k0 + f4);
        }
        __syncthreads();
        #pragma unroll
        for (int kq = 0; kq < 8; kq++) {
            float4 a[8], w[4];
            #pragma unroll
            for (int i = 0; i < 8; i++)
                a[i] = *(const float4*)(As + (8 * ty + i) * 36 + kq * 4);
            #pragma unroll
            for (int j = 0; j < 4; j++)
                w[j] = *(const float4*)(Ws + (4 * tx + j) * 36 + kq * 4);
            #pragma unroll
            for (int i = 0; i < 8; i++)
                #pragma unroll
                for (int j = 0; j < 4; j++)
                    acc[i][j] += a[i].x * w[j].x + a[i].y * w[j].y
                               + a[i].z * w[j].z + a[i].w * w[j].w;
        }
        __syncthreads();
    }

    // stash pre-activations to smem (rows 0-63 primal, 64-127 tangent)
    #pragma unroll
    for (int i = 0; i < 8; i++)
        #pragma unroll
        for (int j = 0; j < 4; j++)
            As[(8 * ty + i) * 33 + 4 * tx + j] = acc[i][j];
    __syncthreads();

    float* hnext  = g_h[(t + 1) & 1];
    float* dhnext = g_dh[(t + 1) & 1];

    #pragma unroll
    for (int it = 0; it < 4; it++) {
        int item = tid + it * 128;          // [0,512): (b, jj)
        int b = item >> 3, jj = item & 7;
        int col = n0 + jj;
        size_t gbase = ((size_t)t * BB + b) * G4 + col;

        float pi = As[b * 33 + jj]       + g_G[gbase];
        float pf = As[b * 33 + 8 + jj]   + g_G[gbase + HH];
        float pg = As[b * 33 + 16 + jj]  + g_G[gbase + 2 * HH];
        float po = As[b * 33 + 24 + jj]  + g_G[gbase + 3 * HH];
        float dhi = As[(64 + b) * 33 + jj];
        float dhf = As[(64 + b) * 33 + 8 + jj];
        float dhg = As[(64 + b) * 33 + 16 + jj];
        float dho = As[(64 + b) * 33 + 24 + jj];

        float g0 = EPSF * g[gbase];
        float g1 = EPSF * g[gbase + HH];
        float g2 = EPSF * g[gbase + 2 * HH];
        float g3 = EPSF * g[gbase + 3 * HH];

        float n2  = g_xn2[t * BB + b] + g_hn2[t * BB + b] + 2.0f;
        float nrm = sqrtf(n2);
        float inv = 1.0f / nrm;
        float s   = (n2 - 2.0f) * inv;

        float iv = 1.0f / (1.0f + expf(-pi));
        float fv = 1.0f / (1.0f + expf(-pf));
        float gv = tanhf(pg);
        float ov = 1.0f / (1.0f + expf(-po));

        float dpi = g0 * (s + inv) + g1 * inv + dhi;
        float dpf = g1 * s + (g2 + g3) * inv + dhf;
        float dpg = g2 * s + (g0 + g1) * inv + dhg;
        float dpo = g3 * s + (g2 + g3) * inv + dho;

        float di  = iv * (1.f - iv) * dpi;
        float df  = fv * (1.f - fv) * dpf;
        float dg  = (1.f - gv * gv) * dpg;
        float dov = ov * (1.f - ov) * dpo;

        int sidx = b * HH + col;
        float c = g_c[sidx], dc = g_dc[sidx];
        float c2  = fv * c + iv * gv;
        float dc2 = df * c + fv * dc + di * gv + iv * dg;
        float tc  = tanhf(c2);
        float h2  = ov * tc;
        float dh2 = dov * tc + ov * (1.f - tc * tc) * dc2;

        g_c[sidx] = c2;  g_dc[sidx] = dc2;
        hnext[sidx] = h2; dhnext[sidx] = dh2;

        size_t obase = ((size_t)t * BB + b) * HH + col;
        out[obase] = h2;
        out[(size_t)TT * BB * HH + obase] = dh2;

        atomicAdd(&g_hn2[(t + 1) * BB + b], h2 * h2);
    }
}

// ---------------- launch ------------------------------------------------------
extern "C" void kernel_launch(void* const* d_in, const int* in_sizes, int n_in,
                              void* d_out, int out_size) {
    const float* x   = (const float*)d_in[0];   // [T,B,D]
    const float* g   = (const float*)d_in[1];   // [T,B,4H]
    const float* Wih = (const float*)d_in[2];   // [4H,D]
    const float* Whh = (const float*)d_in[3];   // [4H,H]
    const float* bih = (const float*)d_in[4];   // [4H]
    const float* bhh = (const float*)d_in[5];   // [4H]
    float* out = (float*)d_out;                 // [2,T,B,H]

    init_kernel<<<256, 256>>>();
    xnorm_kernel<<<TT * BB, 256>>>(x);
    pre_gemm<<<dim3(G4 / 128, (TT * BB) / 128), 256>>>(x, Wih, bih, bhh);
    for (int t = 0; t < TT; t++)
        step_kernel<<<128, 128>>>(t, g, Whh, out);
}

// round 3
// speedup vs baseline: 1.9878x; 1.9878x over previous
#include <cuda_runtime.h>

#define TT 256
#define BB 64
#define DD 1024
#define HH 1024
#define G4 4096
#define EPSF 0.01f
#define NCTA 128
#define NTHR 256

typedef unsigned long long ull;

// ---------------- device scratch -------------------------------------------
static __device__ float  g_G[(size_t)TT * BB * G4];   // x@W_ih.T + b_ih + b_hh
static __device__ float  g_xn2[TT * BB];              // |x_t|^2
static __device__ float  g_hn2[(TT + 1) * BB];        // |h_t|^2 (atomic-accumulated)
static __device__ float2 g_hd[2][BB * HH];            // interleaved (h, dh) ping-pong
static __device__ unsigned g_bar;                     // global step barrier counter

// ---------------- packed f32x2 helpers --------------------------------------
__device__ __forceinline__ void fma2(ull& d, ull a, ull b) {
    asm("fma.rn.f32x2 %0, %1, %2, %0;" : "+l"(d) : "l"(a), "l"(b));
}
__device__ __forceinline__ ull dup2(float v) {
    ull r;
    asm("mov.b64 %0, {%1, %1};" : "=l"(r) : "f"(v));
    return r;
}
__device__ __forceinline__ void unpack2(ull v, float& lo, float& hi) {
    asm("mov.b64 {%0, %1}, %2;" : "=f"(lo), "=f"(hi) : "l"(v));
}

// ---------------- init (runs every replay) ----------------------------------
__global__ void init_kernel() {
    int idx = blockIdx.x * blockDim.x + threadIdx.x;
    int stride = gridDim.x * blockDim.x;
    for (int i = idx; i < BB * HH; i += stride) {
        g_hd[0][i] = make_float2(0.f, 0.f);
        g_hd[1][i] = make_float2(0.f, 0.f);
    }
    for (int i = idx; i < (TT + 1) * BB; i += stride) g_hn2[i] = 0.f;
    if (idx == 0) g_bar = 0u;
}

// ---------------- |x_t|^2 ---------------------------------------------------
__global__ void xnorm_kernel(const float* __restrict__ x) {
    int row = blockIdx.x;                 // t*BB + b
    const float* xr = x + (size_t)row * DD;
    float s = 0.f;
    for (int i = threadIdx.x; i < DD; i += blockDim.x) { float v = xr[i]; s += v * v; }
    __shared__ float red[8];
    #pragma unroll
    for (int o = 16; o > 0; o >>= 1) s += __shfl_xor_sync(0xffffffffu, s, o);
    if ((threadIdx.x & 31) == 0) red[threadIdx.x >> 5] = s;
    __syncthreads();
    if (threadIdx.x < 8) {
        s = red[threadIdx.x];
        #pragma unroll
        for (int o = 4; o > 0; o >>= 1) s += __shfl_xor_sync(0xffu, s, o);
        if (threadIdx.x == 0) g_xn2[row] = s;
    }
}

// ---------------- precompute GEMM: G = x @ W_ih.T + (b_ih + b_hh) -----------
__global__ void __launch_bounds__(256) pre_gemm(const float* __restrict__ x,
                                                const float* __restrict__ Wih,
                                                const float* __restrict__ bih,
                                                const float* __restrict__ bhh) {
    __shared__ __align__(16) float As[128 * 12];
    __shared__ __align__(16) float Bs[8 * 132];
    const int n0 = blockIdx.x * 128;
    const int m0 = blockIdx.y * 128;
    const int tid = threadIdx.x;
    const int tx = tid & 15, ty = tid >> 4;
    const int lrow = tid >> 1, lhalf = tid & 1;

    float acc[8][8];
    #pragma unroll
    for (int i = 0; i < 8; i++)
        #pragma unroll
        for (int j = 0; j < 8; j++) acc[i][j] = 0.f;

    const float* aptr = x   + (size_t)(m0 + lrow) * DD + lhalf * 4;
    const float* bptr = Wih + (size_t)(n0 + lrow) * DD + lhalf * 4;

    for (int k0 = 0; k0 < DD; k0 += 8) {
        float4 av = *(const float4*)(aptr + k0);
        float4 bv = *(const float4*)(bptr + k0);
        *(float4*)(As + lrow * 12 + lhalf * 4) = av;
        Bs[(lhalf * 4 + 0) * 132 + lrow] = bv.x;
        Bs[(lhalf * 4 + 1) * 132 + lrow] = bv.y;
        Bs[(lhalf * 4 + 2) * 132 + lrow] = bv.z;
        Bs[(lhalf * 4 + 3) * 132 + lrow] = bv.w;
        __syncthreads();
        #pragma unroll
        for (int kq = 0; kq < 2; kq++) {
            float4 a[8];
            #pragma unroll
            for (int i = 0; i < 8; i++)
                a[i] = *(const float4*)(As + (8 * ty + i) * 12 + kq * 4);
            float4 b0[4], b1[4];
            #pragma unroll
            for (int e = 0; e < 4; e++) {
                b0[e] = *(const float4*)(Bs + (kq * 4 + e) * 132 + 8 * tx);
                b1[e] = *(const float4*)(Bs + (kq * 4 + e) * 132 + 8 * tx + 4);
            }
            #pragma unroll
            for (int i = 0; i < 8; i++) {
                const float* ai = reinterpret_cast<const float*>(&a[i]);
                #pragma unroll
                for (int e = 0; e < 4; e++) {
                    const float* p0 = reinterpret_cast<const float*>(&b0[e]);
                    const float* p1 = reinterpret_cast<const float*>(&b1[e]);
                    float av_ = ai[e];
                    #pragma unroll
                    for (int j = 0; j < 4; j++) {
                        acc[i][j]     += av_ * p0[j];
                        acc[i][4 + j] += av_ * p1[j];
                    }
                }
            }
        }
        __syncthreads();
    }

    float bsum[8];
    #pragma unroll
    for (int j = 0; j < 8; j++) {
        int n = n0 + 8 * tx + j;
        bsum[j] = bih[n] + bhh[n];
    }
    #pragma unroll
    for (int i = 0; i < 8; i++) {
        size_t row = (size_t)(m0 + 8 * ty + i);
        float* dst = g_G + row * G4 + n0 + 8 * tx;
        float4 o0, o1;
        o0.x = acc[i][0] + bsum[0]; o0.y = acc[i][1] + bsum[1];
        o0.z = acc[i][2] + bsum[2]; o0.w = acc[i][3] + bsum[3];
        o1.x = acc[i][4] + bsum[4]; o1.y = acc[i][5] + bsum[5];
        o1.z = acc[i][6] + bsum[6]; o1.w = acc[i][7] + bsum[7];
        *(float4*)dst       = o0;
        *(float4*)(dst + 4) = o1;
    }
}

// ---------------- persistent recurrence kernel -------------------------------
// SMEM layout (dynamic, 174080 B):
//   Ws   : float [1024][34]      (W_hh slice, [k][c], c = gate*8 + jj)   139264 B
//   As2  : ull   [2][64*34]      ((h,dh) tiles, [b][k], double-buffered)  34816 B
#define WS_BYTES  (1024 * 34 * 4)
#define AS_ULLS   (64 * 34)
#define SMEM_TOTAL (WS_BYTES + 2 * AS_ULLS * 8)

__global__ void __launch_bounds__(NTHR, 1)
persist_kernel(const float* __restrict__ gp, const float* __restrict__ Whh,
               float* __restrict__ out) {
    extern __shared__ char sraw[];
    float* Ws  = (float*)sraw;
    ull*   As2 = (ull*)(sraw + WS_BYTES);

    const int tid = threadIdx.x;
    const int n0  = blockIdx.x * 8;          // 8 h-columns owned by this CTA
    const int tx  = tid & 15;                // col pair (2tx, 2tx+1) of 32 gate-cols
    const int ty  = tid >> 4;                // rows 4ty..4ty+3 (b)
    const int jj  = tid & 7;                 // elementwise: h-col within CTA
    const int b0  = tid >> 3;                // elementwise: batch rows b0, b0+32
    const int col = n0 + jj;
    const int lr  = tid >> 2;                // loader: batch row
    const int lq  = tid & 3;                 // loader: float4 segment

    // ---- one-time: W_hh slice -> SMEM, Ws[k*34 + c] = Whh[gate*H + col][k]
    #pragma unroll 1
    for (int c = 0; c < 32; c++) {
        int gcol = (c >> 3) * HH + n0 + (c & 7);
        float4 v = __ldg((const float4*)(Whh + (size_t)gcol * HH) + tid);
        int k = tid * 4;
        Ws[(k + 0) * 34 + c] = v.x;
        Ws[(k + 1) * 34 + c] = v.y;
        Ws[(k + 2) * 34 + c] = v.z;
        Ws[(k + 3) * 34 + c] = v.w;
    }

    float cst[2]  = {0.f, 0.f};
    float dcst[2] = {0.f, 0.f};
    const size_t OFF = (size_t)TT * BB * HH;

    for (int t = 0; t < TT; t++) {
        // ---- prefetch elementwise operands (consumed ~30K cycles later) ----
        float Gr[2][4], Pr[2][4], xnv[2], hnv[2];
        #pragma unroll
        for (int itm = 0; itm < 2; itm++) {
            int b = b0 + 32 * itm;
            size_t gb = ((size_t)t * BB + b) * G4 + col;
            #pragma unroll
            for (int q = 0; q < 4; q++) {
                Gr[itm][q] = __ldg(&g_G[gb + q * HH]);
                Pr[itm][q] = EPSF * __ldg(&gp[gb + q * HH]);
            }
            xnv[itm] = __ldg(&g_xn2[t * BB + b]);
            hnv[itm] = __ldcg(&g_hn2[t * BB + b]);   // atomics wrote it: bypass L1
        }

        // ---- recurrent GEMM: [64 x 1024 (h,dh)] x Ws -> 64 x 32 packed -----
        ull acc[4][2];
        #pragma unroll
        for (int i = 0; i < 4; i++) { acc[i][0] = 0ull; acc[i][1] = 0ull; }

        const float2* hsrc = g_hd[t & 1];
        const float4* lrow = (const float4*)(hsrc + (size_t)lr * HH);

        // prologue: load + stage chunk 0
        float4 stg[4];
        #pragma unroll
        for (int m = 0; m < 4; m++)
            stg[m] = __ldcg(lrow + (lq + 4 * m));
        {
            ull* buf = As2;
            #pragma unroll
            for (int m = 0; m < 4; m++) {
                int j = lq + 4 * m;                      // float4 index in row
                *(float4*)&buf[lr * 34 + 2 * j] = stg[m];
            }
        }
        __syncthreads();

        #pragma unroll 1
        for (int c = 0; c < 32; c++) {
            const int cur = c & 1;
            if (c < 31) {
                #pragma unroll
                for (int m = 0; m < 4; m++)
                    stg[m] = __ldcg(lrow + ((c + 1) * 16 + lq + 4 * m));
            }
            // compute on buffer cur
            const ull*   Asb  = As2 + cur * AS_ULLS;
            const float* wrow = Ws + (c * 32) * 34 + 2 * tx;
            #pragma unroll
            for (int kk = 0; kk < 32; kk += 2) {
                float2 wv0 = *(const float2*)(wrow + (kk    ) * 34);
                float2 wv1 = *(const float2*)(wrow + (kk + 1) * 34);
                ull w00 = dup2(wv0.x), w01 = dup2(wv0.y);
                ull w10 = dup2(wv1.x), w11 = dup2(wv1.y);
                #pragma unroll
                for (int i = 0; i < 4; i++) {
                    ulonglong2 av = *(const ulonglong2*)&Asb[(4 * ty + i) * 34 + kk];
                    fma2(acc[i][0], av.x, w00);
                    fma2(acc[i][1], av.x, w01);
                    fma2(acc[i][0], av.y, w10);
                    fma2(acc[i][1], av.y, w11);
                }
            }
            if (c < 31) {
                ull* nbuf = As2 + (cur ^ 1) * AS_ULLS;   // last read 2 chunks ago: safe
                #pragma unroll
                for (int m = 0; m < 4; m++) {
                    int j = (c + 1) * 16 + lq + 4 * m;
                    *(float4*)&nbuf[lr * 34 + 2 * (j & 15)] = stg[m];
                }
                __syncthreads();
            }
        }

        // ---- stage accumulators to SMEM for gate redistribution -------------
        __syncthreads();                                  // all compute done
        ull* ps = As2;                                    // reuse buffer 0
        #pragma unroll
        for (int i = 0; i < 4; i++) {
            ulonglong2 v; v.x = acc[i][0]; v.y = acc[i][1];
            *(ulonglong2*)&ps[(4 * ty + i) * 34 + 2 * tx] = v;
        }
        __syncthreads();

        // ---- fused LSTM + MAGE elementwise ----------------------------------
        float2* hnxt = g_hd[(t + 1) & 1];
        #pragma unroll
        for (int itm = 0; itm < 2; itm++) {
            int b = b0 + 32 * itm;
            float phi, thi, phf, thf, phg, thg, pho, tho;
            unpack2(ps[b * 34 + jj],      phi, thi);
            unpack2(ps[b * 34 + jj +  8], phf, thf);
            unpack2(ps[b * 34 + jj + 16], phg, thg);
            unpack2(ps[b * 34 + jj + 24], pho, tho);

            float pi = phi + Gr[itm][0];
            float pf = phf + Gr[itm][1];
            float pg = phg + Gr[itm][2];
            float po = pho + Gr[itm][3];

            float n2  = xnv[itm] + hnv[itm] + 2.0f;
            float nrm = sqrtf(n2);
            float inv = 1.0f / nrm;
            float s   = (n2 - 2.0f) * inv;

            float iv = 1.0f / (1.0f + __expf(-pi));
            float fv = 1.0f / (1.0f + __expf(-pf));
            float gv = __tanhf(pg);
            float ov = 1.0f / (1.0f + __expf(-po));

            float g0 = Pr[itm][0], g1 = Pr[itm][1], g2 = Pr[itm][2], g3 = Pr[itm][3];
            float dpi = g0 * (s + inv) + g1 * inv + thi;
            float dpf = g1 * s + (g2 + g3) * inv + thf;
            float dpg = g2 * s + (g0 + g1) * inv + thg;
            float dpo = g3 * s + (g2 + g3) * inv + tho;

            float di  = iv * (1.f - iv) * dpi;
            float df  = fv * (1.f - fv) * dpf;
            float dg  = (1.f - gv * gv) * dpg;
            float dov = ov * (1.f - ov) * dpo;

            float c2  = fv * cst[itm] + iv * gv;
            float dc2 = df * cst[itm] + fv * dcst[itm] + di * gv + iv * dg;
            float tc  = __tanhf(c2);
            float h2  = ov * tc;
            float dh2 = dov * tc + ov * (1.f - tc * tc) * dc2;
            cst[itm] = c2; dcst[itm] = dc2;

            hnxt[b * HH + col] = make_float2(h2, dh2);
            size_t ob = ((size_t)t * BB + b) * HH + col;
            out[ob]       = h2;
            out[OFF + ob] = dh2;

            float sum = h2 * h2;
            #pragma unroll
            for (int o = 1; o < 8; o <<= 1)
                sum += __shfl_xor_sync(0xffffffffu, sum, o);
            if (jj == 0) atomicAdd(&g_hn2[(t + 1) * BB + b], sum);
        }

        // ---- grid barrier ----------------------------------------------------
        __threadfence();
        __syncthreads();
        if (tid == 0) {
            atomicAdd(&g_bar, 1u);
            unsigned tgt = (unsigned)(t + 1) * NCTA;
            unsigned v;
            do {
                asm volatile("ld.acquire.gpu.b32 %0, [%1];" : "=r"(v) : "l"(&g_bar) : "memory");
            } while (v < tgt);
        }
        __syncthreads();
    }
}

// ---------------- launch ------------------------------------------------------
extern "C" void kernel_launch(void* const* d_in, const int* in_sizes, int n_in,
                              void* d_out, int out_size) {
    const float* x   = (const float*)d_in[0];   // [T,B,D]
    const float* g   = (const float*)d_in[1];   // [T,B,4H]
    const float* Wih = (const float*)d_in[2];   // [4H,D]
    const float* Whh = (const float*)d_in[3];   // [4H,H]
    const float* bih = (const float*)d_in[4];   // [4H]
    const float* bhh = (const float*)d_in[5];   // [4H]
    float* out = (float*)d_out;                 // [2,T,B,H]

    cudaFuncSetAttribute(persist_kernel, cudaFuncAttributeMaxDynamicSharedMemorySize,
                         SMEM_TOTAL);

    init_kernel<<<256, 256>>>();
    xnorm_kernel<<<TT * BB, 256>>>(x);
    pre_gemm<<<dim3(G4 / 128, (TT * BB) / 128), 256>>>(x, Wih, bih, bhh);
    persist_kernel<<<NCTA, NTHR, SMEM_TOTAL>>>(g, Whh, out);
}

// round 4
// speedup vs baseline: 1.9949x; 1.0035x over previous
#include <cuda_runtime.h>

#define TT 256
#define BB 64
#define DD 1024
#define HH 1024
#define G4 4096
#define EPSF 0.01f
#define NCTA 128
#define NTHR 256

typedef unsigned long long ull;

// ---------------- device scratch -------------------------------------------
static __device__ float  g_G[(size_t)TT * BB * G4];   // x@W_ih.T + b_ih + b_hh
static __device__ float  g_xn2[TT * BB];              // |x_t|^2
static __device__ float  g_hn2[(TT + 1) * BB];        // |h_t|^2 (atomic-accumulated)
static __device__ float2 g_hd[2][BB * HH];            // interleaved (h, dh) ping-pong
static __device__ unsigned g_bar;                     // global step barrier counter

// ---------------- packed f32x2 helpers --------------------------------------
__device__ __forceinline__ void fma2(ull& d, ull a, ull b) {
    asm("fma.rn.f32x2 %0, %1, %2, %0;" : "+l"(d) : "l"(a), "l"(b));
}
__device__ __forceinline__ ull dup2(float v) {
    ull r;
    asm("mov.b64 %0, {%1, %1};" : "=l"(r) : "f"(v));
    return r;
}
__device__ __forceinline__ void unpack2(ull v, float& lo, float& hi) {
    asm("mov.b64 {%0, %1}, %2;" : "=f"(lo), "=f"(hi) : "l"(v));
}

// ---------------- init (runs every replay) ----------------------------------
__global__ void init_kernel() {
    int idx = blockIdx.x * blockDim.x + threadIdx.x;
    int stride = gridDim.x * blockDim.x;
    for (int i = idx; i < BB * HH; i += stride) {
        g_hd[0][i] = make_float2(0.f, 0.f);
        g_hd[1][i] = make_float2(0.f, 0.f);
    }
    for (int i = idx; i < (TT + 1) * BB; i += stride) g_hn2[i] = 0.f;
    if (idx == 0) g_bar = 0u;
}

// ---------------- |x_t|^2 ---------------------------------------------------
__global__ void xnorm_kernel(const float* __restrict__ x) {
    int row = blockIdx.x;                 // t*BB + b
    const float* xr = x + (size_t)row * DD;
    float s = 0.f;
    for (int i = threadIdx.x; i < DD; i += blockDim.x) { float v = xr[i]; s += v * v; }
    __shared__ float red[8];
    #pragma unroll
    for (int o = 16; o > 0; o >>= 1) s += __shfl_xor_sync(0xffffffffu, s, o);
    if ((threadIdx.x & 31) == 0) red[threadIdx.x >> 5] = s;
    __syncthreads();
    if (threadIdx.x < 8) {
        s = red[threadIdx.x];
        #pragma unroll
        for (int o = 4; o > 0; o >>= 1) s += __shfl_xor_sync(0xffu, s, o);
        if (threadIdx.x == 0) g_xn2[row] = s;
    }
}

// ---------------- precompute GEMM: G = x @ W_ih.T + (b_ih + b_hh) -----------
__global__ void __launch_bounds__(256) pre_gemm(const float* __restrict__ x,
                                                const float* __restrict__ Wih,
                                                const float* __restrict__ bih,
                                                const float* __restrict__ bhh) {
    __shared__ __align__(16) float As[128 * 12];
    __shared__ __align__(16) float Bs[8 * 132];
    const int n0 = blockIdx.x * 128;
    const int m0 = blockIdx.y * 128;
    const int tid = threadIdx.x;
    const int tx = tid & 15, ty = tid >> 4;
    const int lrow = tid >> 1, lhalf = tid & 1;

    float acc[8][8];
    #pragma unroll
    for (int i = 0; i < 8; i++)
        #pragma unroll
        for (int j = 0; j < 8; j++) acc[i][j] = 0.f;

    const float* aptr = x   + (size_t)(m0 + lrow) * DD + lhalf * 4;
    const float* bptr = Wih + (size_t)(n0 + lrow) * DD + lhalf * 4;

    for (int k0 = 0; k0 < DD; k0 += 8) {
        float4 av = *(const float4*)(aptr + k0);
        float4 bv = *(const float4*)(bptr + k0);
        *(float4*)(As + lrow * 12 + lhalf * 4) = av;
        Bs[(lhalf * 4 + 0) * 132 + lrow] = bv.x;
        Bs[(lhalf * 4 + 1) * 132 + lrow] = bv.y;
        Bs[(lhalf * 4 + 2) * 132 + lrow] = bv.z;
        Bs[(lhalf * 4 + 3) * 132 + lrow] = bv.w;
        __syncthreads();
        #pragma unroll
        for (int kq = 0; kq < 2; kq++) {
            float4 a[8];
            #pragma unroll
            for (int i = 0; i < 8; i++)
                a[i] = *(const float4*)(As + (8 * ty + i) * 12 + kq * 4);
            float4 b0[4], b1[4];
            #pragma unroll
            for (int e = 0; e < 4; e++) {
                b0[e] = *(const float4*)(Bs + (kq * 4 + e) * 132 + 8 * tx);
                b1[e] = *(const float4*)(Bs + (kq * 4 + e) * 132 + 8 * tx + 4);
            }
            #pragma unroll
            for (int i = 0; i < 8; i++) {
                const float* ai = reinterpret_cast<const float*>(&a[i]);
                #pragma unroll
                for (int e = 0; e < 4; e++) {
                    const float* p0 = reinterpret_cast<const float*>(&b0[e]);
                    const float* p1 = reinterpret_cast<const float*>(&b1[e]);
                    float av_ = ai[e];
                    #pragma unroll
                    for (int j = 0; j < 4; j++) {
                        acc[i][j]     += av_ * p0[j];
                        acc[i][4 + j] += av_ * p1[j];
                    }
                }
            }
        }
        __syncthreads();
    }

    float bsum[8];
    #pragma unroll
    for (int j = 0; j < 8; j++) {
        int n = n0 + 8 * tx + j;
        bsum[j] = bih[n] + bhh[n];
    }
    #pragma unroll
    for (int i = 0; i < 8; i++) {
        size_t row = (size_t)(m0 + 8 * ty + i);
        float* dst = g_G + row * G4 + n0 + 8 * tx;
        float4 o0, o1;
        o0.x = acc[i][0] + bsum[0]; o0.y = acc[i][1] + bsum[1];
        o0.z = acc[i][2] + bsum[2]; o0.w = acc[i][3] + bsum[3];
        o1.x = acc[i][4] + bsum[4]; o1.y = acc[i][5] + bsum[5];
        o1.z = acc[i][6] + bsum[6]; o1.w = acc[i][7] + bsum[7];
        *(float4*)dst       = o0;
        *(float4*)(dst + 4) = o1;
    }
}

// ---------------- persistent recurrence kernel -------------------------------
// 256 threads = 8 warps. warp w: k-slice ks=w&3 (256 k), row-half rh=w>>2 (32 b).
// lane: cg=lane>>3 (cols 8cg..8cg+7 of 32 gate-cols), rg=lane&7
// (rows rh*32 + rg + 8i, i=0..3). 32 packed ull accumulators per thread.
// SMEM: Wsm [1024][32] f32 (131072 B) + per-warp A windows [8][32][18] ull
// (36864 B, overlaid by the 32 KB reduction buffer after compute).
#define WS_BYTES  (1024 * 32 * 4)
#define AW_STRIDE 18
#define AW_ULLS   (32 * AW_STRIDE)
#define SMEM_TOTAL (WS_BYTES + 8 * AW_ULLS * 8)

__global__ void __launch_bounds__(NTHR, 1)
persist_kernel(const float* __restrict__ gp, const float* __restrict__ Whh,
               float* __restrict__ out) {
    extern __shared__ char sraw[];
    float* Wsm = (float*)sraw;
    ull*   AwB = (ull*)(sraw + WS_BYTES);

    const int tid  = threadIdx.x;
    const int n0   = blockIdx.x * 8;
    const int w    = tid >> 5;
    const int lane = tid & 31;
    const int ks   = w & 3;
    const int rh   = w >> 2;
    const int cg   = lane >> 3;
    const int rg   = lane & 7;
    const int jj   = tid & 7;
    const int bidx = tid >> 3;
    const int ksbase = ks * 256;

    ull* Aw = AwB + w * AW_ULLS;

    // ---- one-time: W_hh slice -> SMEM, Wsm[k*32 + c] = Whh[(c>>3)*H + n0+(c&7)][k]
    #pragma unroll 1
    for (int c = 0; c < 32; c++) {
        int gcol = (c >> 3) * HH + n0 + (c & 7);
        float4 v = __ldg((const float4*)(Whh + (size_t)gcol * HH) + tid);
        int k = tid * 4;
        Wsm[(k + 0) * 32 + c] = v.x;
        Wsm[(k + 1) * 32 + c] = v.y;
        Wsm[(k + 2) * 32 + c] = v.z;
        Wsm[(k + 3) * 32 + c] = v.w;
    }

    // elementwise item (b, jj) per pass p: fixed across steps
    int bitem[2];
    #pragma unroll
    for (int p = 0; p < 2; p++) bitem[p] = 16 * p + bidx + (bidx & 16);

    float cst[2]  = {0.f, 0.f};
    float dcst[2] = {0.f, 0.f};
    const size_t OFF = (size_t)TT * BB * HH;

    for (int t = 0; t < TT; t++) {
        // ---- prefetch elementwise operands --------------------------------
        float Gr[2][4], Pr[2][4], xnv[2], hnv[2];
        #pragma unroll
        for (int p = 0; p < 2; p++) {
            int b = bitem[p];
            size_t gb = ((size_t)t * BB + b) * G4 + n0 + jj;
            #pragma unroll
            for (int q = 0; q < 4; q++) {
                Gr[p][q] = __ldg(&g_G[gb + q * HH]);
                Pr[p][q] = EPSF * __ldg(&gp[gb + q * HH]);
            }
            xnv[p] = __ldg(&g_xn2[t * BB + b]);
            hnv[p] = __ldcg(&g_hn2[t * BB + b]);
        }

        // ---- split-K GEMM ---------------------------------------------------
        ull acc[4][8];
        #pragma unroll
        for (int i = 0; i < 4; i++)
            #pragma unroll
            for (int cc = 0; cc < 8; cc++) acc[i][cc] = 0ull;

        const float2* hsrc = g_hd[t & 1];
        const float4* lrowp[8];
        #pragma unroll
        for (int m = 0; m < 8; m++)
            lrowp[m] = (const float4*)(hsrc + (size_t)(rh * 32 + m * 4 + cg) * HH);

        // prologue: chunk 0 into this warp's window
        #pragma unroll
        for (int m = 0; m < 8; m++) {
            float4 v = __ldcg(lrowp[m] + (ksbase >> 1) + rg);
            *(float4*)&Aw[(m * 4 + cg) * AW_STRIDE + rg * 2] = v;
        }
        __syncwarp();

        #pragma unroll 1
        for (int c = 0; c < 16; c++) {
            const int k0 = ksbase + c * 16;
            float4 nstg[8];
            if (c < 15) {
                #pragma unroll
                for (int m = 0; m < 8; m++)
                    nstg[m] = __ldcg(lrowp[m] + ((k0 + 16) >> 1) + rg);
            }
            #pragma unroll
            for (int j = 0; j < 8; j++) {
                const int k = k0 + 2 * j;
                float4 w0 = *(const float4*)&Wsm[k * 32 + 8 * cg];
                float4 w1 = *(const float4*)&Wsm[k * 32 + 8 * cg + 4];
                float4 w2 = *(const float4*)&Wsm[(k + 1) * 32 + 8 * cg];
                float4 w3 = *(const float4*)&Wsm[(k + 1) * 32 + 8 * cg + 4];
                const float* f0 = (const float*)&w0;
                const float* f1 = (const float*)&w1;
                const float* f2 = (const float*)&w2;
                const float* f3 = (const float*)&w3;
                ull W0[8], W1[8];
                #pragma unroll
                for (int e = 0; e < 4; e++) {
                    W0[e]     = dup2(f0[e]);
                    W0[4 + e] = dup2(f1[e]);
                    W1[e]     = dup2(f2[e]);
                    W1[4 + e] = dup2(f3[e]);
                }
                #pragma unroll
                for (int i = 0; i < 4; i++) {
                    ulonglong2 av =
                        *(const ulonglong2*)&Aw[(rg + 8 * i) * AW_STRIDE + 2 * j];
                    #pragma unroll
                    for (int cc = 0; cc < 8; cc++) {
                        fma2(acc[i][cc], av.x, W0[cc]);
                        fma2(acc[i][cc], av.y, W1[cc]);
                    }
                }
            }
            __syncwarp();
            if (c < 15) {
                #pragma unroll
                for (int m = 0; m < 8; m++)
                    *(float4*)&Aw[(m * 4 + cg) * AW_STRIDE + rg * 2] = nstg[m];
                __syncwarp();
            }
        }

        // ---- reduce partials + fused elementwise, two passes ----------------
        __syncthreads();                      // all warps done; Awin reusable
        ull* red = AwB;                       // overlay: [rh*4+ks][16][32] ull

        float2* hnxt = g_hd[(t + 1) & 1];

        #pragma unroll 1
        for (int p = 0; p < 2; p++) {
            #pragma unroll
            for (int i2 = 0; i2 < 2; i2++) {
                int i = 2 * p + i2;
                int lrow = rg + 8 * i2;
                ull* dst = &red[(((rh * 4 + ks) * 16 + lrow) * 32) + 8 * cg];
                #pragma unroll
                for (int e = 0; e < 4; e++) {
                    ulonglong2 v;
                    v.x = acc[i][2 * e];
                    v.y = acc[i][2 * e + 1];
                    *(ulonglong2*)&dst[2 * e] = v;
                }
            }
            __syncthreads();

            {
                int b = bitem[p];
                int rhb = b >> 5;
                int lrow = b & 15;
                float ph[4], th[4];
                #pragma unroll
                for (int gt = 0; gt < 4; gt++) {
                    int col = gt * 8 + jj;
                    float sl = 0.f, sh = 0.f;
                    #pragma unroll
                    for (int q = 0; q < 4; q++) {
                        float a, bb;
                        unpack2(red[((rhb * 4 + q) * 16 + lrow) * 32 + col], a, bb);
                        sl += a; sh += bb;
                    }
                    ph[gt] = sl; th[gt] = sh;
                }

                float pi = ph[0] + Gr[p][0];
                float pf = ph[1] + Gr[p][1];
                float pg = ph[2] + Gr[p][2];
                float po = ph[3] + Gr[p][3];

                float n2  = xnv[p] + hnv[p] + 2.0f;
                float nrm = sqrtf(n2);
                float inv = 1.0f / nrm;
                float s   = (n2 - 2.0f) * inv;

                float iv = 1.0f / (1.0f + __expf(-pi));
                float fv = 1.0f / (1.0f + __expf(-pf));
                float gv = __tanhf(pg);
                float ov = 1.0f / (1.0f + __expf(-po));

                float g0 = Pr[p][0], g1 = Pr[p][1], g2 = Pr[p][2], g3 = Pr[p][3];
                float dpi = g0 * (s + inv) + g1 * inv + th[0];
                float dpf = g1 * s + (g2 + g3) * inv + th[1];
                float dpg = g2 * s + (g0 + g1) * inv + th[2];
                float dpo = g3 * s + (g2 + g3) * inv + th[3];

                float di  = iv * (1.f - iv) * dpi;
                float df  = fv * (1.f - fv) * dpf;
                float dg  = (1.f - gv * gv) * dpg;
                float dov = ov * (1.f - ov) * dpo;

                float c2  = fv * cst[p] + iv * gv;
                float dc2 = df * cst[p] + fv * dcst[p] + di * gv + iv * dg;
                float tc  = __tanhf(c2);
                float h2  = ov * tc;
                float dh2 = dov * tc + ov * (1.f - tc * tc) * dc2;
                cst[p] = c2; dcst[p] = dc2;

                int col = n0 + jj;
                hnxt[b * HH + col] = make_float2(h2, dh2);
                size_t ob = ((size_t)t * BB + b) * HH + col;
                out[ob]       = h2;
                out[OFF + ob] = dh2;

                float sum = h2 * h2;
                #pragma unroll
                for (int o = 1; o < 8; o <<= 1)
                    sum += __shfl_xor_sync(0xffffffffu, sum, o);
                if (jj == 0) atomicAdd(&g_hn2[(t + 1) * BB + b], sum);
            }
            __syncthreads();
        }

        // ---- grid barrier ----------------------------------------------------
        __threadfence();
        if (tid == 0) {
            atomicAdd(&g_bar, 1u);
            unsigned tgt = (unsigned)(t + 1) * NCTA;
            unsigned v;
            do {
                asm volatile("ld.acquire.gpu.b32 %0, [%1];" : "=r"(v) : "l"(&g_bar) : "memory");
            } while (v < tgt);
        }
        __syncthreads();
    }
}

// ---------------- launch ------------------------------------------------------
extern "C" void kernel_launch(void* const* d_in, const int* in_sizes, int n_in,
                              void* d_out, int out_size) {
    const float* x   = (const float*)d_in[0];   // [T,B,D]
    const float* g   = (const float*)d_in[1];   // [T,B,4H]
    const float* Wih = (const float*)d_in[2];   // [4H,D]
    const float* Whh = (const float*)d_in[3];   // [4H,H]
    const float* bih = (const float*)d_in[4];   // [4H]
    const float* bhh = (const float*)d_in[5];   // [4H]
    float* out = (float*)d_out;                 // [2,T,B,H]

    cudaFuncSetAttribute(persist_kernel, cudaFuncAttributeMaxDynamicSharedMemorySize,
                         SMEM_TOTAL);

    init_kernel<<<256, 256>>>();
    xnorm_kernel<<<TT * BB, 256>>>(x);
    pre_gemm<<<dim3(G4 / 128, (TT * BB) / 128), 256>>>(x, Wih, bih, bhh);
    persist_kernel<<<NCTA, NTHR, SMEM_TOTAL>>>(g, Whh, out);
}